// round 10
// baseline (speedup 1.0000x reference)
#include <cuda_runtime.h>

// ---------------------------------------------------------------------------
// Micromagnetic LLG solver (RK4, 5-pt exchange laplacian, SOT, demag-z).
// Round 9:
//   - NEIGHBOR-ONLY synchronization: per-tile monotone flags; each CTA waits
//     only on its <=8 surrounding tiles (self-timed wavefront, no global
//     barrier, no same-address atomic serialization, tiles may skew in time)
//   - body reverted to proven round-7 config: NT=512, NQ=4, 2 replicas,
//     halo-fused RK4 (4 stages/step), 32x32 interior + halo 4, shrinking
//     stage cone, float4 smem ping-pong stencil
// ---------------------------------------------------------------------------

#define NXg 256
#define NYg 256
#define NCELL (NXg * NYg)
#define TSTEPS 256
#define NSRC 3
#define NPROBE 5
#define RELAX_STEPS 100

#define NB 128          // 2 replicas x 64 tiles, 1 CTA/SM, single wave
#define NT 512
#define HALO 4
#define EXT 40          // 32 + 2*4
#define MAXC (EXT * EXT)  // 1600
#define NQ 4
#define SMEM_BYTES (2 * MAXC * (int)sizeof(float4))   // 51200

// [replica][parity][cell]
__device__ float4 g_fld[2][2][NCELL];
// per-tile progress flags: number of published states (monotone within a run)
__device__ volatile unsigned int g_flag[2][64];

__global__ void reset_kernel() {
    if (threadIdx.x < 128) g_flag[threadIdx.x >> 6][threadIdx.x & 63] = 0u;
}

__global__ void __launch_bounds__(NT, 1)
mm_solver_kernel(const float* __restrict__ sigarr,   // [2, TSTEPS, NSRC]
                 const float* __restrict__ Bext,     // [1,3,NX,NY]
                 const float* __restrict__ msat,
                 const int*   __restrict__ srcp,     // [NSRC,2]
                 const int*   __restrict__ probep,   // [NPROBE,2]
                 const int*   __restrict__ fb,
                 float*       __restrict__ out)      // [2, TSTEPS, NPROBE]
{
    extern __shared__ float4 sb4[];    // [2][MAXC] ping-pong

    const int tid = threadIdx.x;
    const int r  = blockIdx.x >> 6;       // replica = signal index
    const int tb = blockIdx.x & 63;
    const int tx = tb >> 3, ty = tb & 7;
    const int x0 = tx * 32, y0 = ty * 32;

    // Which neighbor-tile flag does this thread poll? Threads 0..8 cover the
    // 3x3 tile neighborhood (self included; self is trivially satisfied).
    int ntid = -1;
    if (tid < 9) {
        int nx2 = tx + tid / 3 - 1, ny2 = ty + tid % 3 - 1;
        if (nx2 >= 0 && nx2 < 8 && ny2 >= 0 && ny2 < 8) ntid = nx2 * 8 + ny2;
    }

    const float Msat = msat[0];
    const int finalb = fb[0];
    const float ce = (float)(2.0 * 3.5e-12 / ((double)Msat * (5e-8 * 5e-8)));
    const float cd = (float)(-(1.2566370614359172e-06) * (double)Msat);
    const float h  = (float)(175950000000.0 * 5e-12);
    const float h6 = (float)((175950000000.0 * 5e-12) / 6.0);
    const float C_SOT = 1.0e-4f;

    // meta bits: [0:3)=limp1 (stage st computed iff st < limp1), bit3=valid,
    //            bit4=interior, [8:16)=src idx+1, [16:24)=probe idx+1
    int meta[NQ], nbN[NQ], nbS[NQ], nbW[NQ], nbE[NQ], ig[NQ];
    float Bcx[NQ], Bcy[NQ], Bcz[NQ];
    float m0x[NQ], m0y[NQ], m0z[NQ];
    float mrelz[NQ];

#pragma unroll
    for (int q = 0; q < NQ; ++q) {
        int c  = tid + q * NT;
        int cc = (c < MAXC) ? c : 0;
        int sx = cc / EXT, sy = cc % EXT;
        int gx = x0 - HALO + sx, gy = y0 - HALO + sy;
        bool valid = (c < MAXC) && gx >= 0 && gx < NXg && gy >= 0 && gy < NYg;
        bool inter = valid && gx >= x0 && gx < x0 + 32 && gy >= y0 && gy < y0 + 32;
        // ring distance d = max outward distance from the 32x32 interior
        int dxn = (sx < HALO) ? (HALO - sx) : (sx >= HALO + 32 ? sx - (HALO + 31) : 0);
        int dyn = (sy < HALO) ? (HALO - sy) : (sy >= HALO + 32 ? sy - (HALO + 31) : 0);
        int d = dxn > dyn ? dxn : dyn;
        int limp1 = valid ? (4 - d) : 0;           // stages computed: st < limp1
        if (limp1 < 0) limp1 = 0;
        // neighbor clamp-to-self at physical edges (pad mode='edge'); ext-edge
        // clamps only ever feed rings outside the dependence cone
        nbN[q] = (sx > 0       && gx > 0      ) ? cc - EXT : cc;
        nbS[q] = (sx < EXT - 1 && gx < NXg - 1) ? cc + EXT : cc;
        nbW[q] = (sy > 0       && gy > 0      ) ? cc - 1   : cc;
        nbE[q] = (sy < EXT - 1 && gy < NYg - 1) ? cc + 1   : cc;
        int gxc = gx < 0 ? 0 : (gx > NXg - 1 ? NXg - 1 : gx);
        int gyc = gy < 0 ? 0 : (gy > NYg - 1 ? NYg - 1 : gy);
        int ign = gxc * NYg + gyc;
        ig[q] = ign;
        Bcx[q] = Bext[ign];
        Bcy[q] = Bext[NCELL + ign];
        Bcz[q] = Bext[2 * NCELL + ign];
        int sj = 0, pj = 0;
        if (valid) {
#pragma unroll
            for (int k2 = 0; k2 < NSRC; ++k2)
                if (srcp[2 * k2] == gx && srcp[2 * k2 + 1] == gy) sj = k2 + 1;
            if (inter) {
#pragma unroll
                for (int k2 = 0; k2 < NPROBE; ++k2)
                    if (probep[2 * k2] == gx && probep[2 * k2 + 1] == gy) pj = k2 + 1;
            }
        }
        meta[q] = limp1 | (valid ? 8 : 0) | (inter ? 16 : 0) | (sj << 8) | (pj << 16);
        m0x[q] = 0.0f; m0y[q] = 1.0f; m0z[q] = 0.0f;
        mrelz[q] = 0.0f;
        if (inter) g_fld[r][0][ign] = make_float4(0.0f, 1.0f, 0.0f, 0.0f);
    }

    // publish initial state (flag = number of published states)
    __syncthreads();
    if (tid == 0) {
        __threadfence();
        g_flag[r][tb] = 1u;
    }

    unsigned int cv = 1;   // states required from neighbors before each step
    int cur = 0;

    float sx_[NQ], sy_[NQ], sz_[NQ], ax_[NQ], ay_[NQ], az_[NQ], sg[NQ];

    // ---- unified step loop: 100 relax + 256 run ----
#pragma unroll 1
    for (int i = 0; i < RELAX_STEPS + TSTEPS; ++i) {
        const bool run = (i >= RELAX_STEPS);
        const int  t   = i - RELAX_STEPS;
        const float alpha = run ? 0.01f : 0.5f;
        const float inv   = run ? (1.0f / (1.0f + 0.01f * 0.01f))
                                : (1.0f / (1.0f + 0.5f * 0.5f));
        const float* sgb = sigarr + (r * TSTEPS + (run ? t : 0)) * NSRC;

        // wait: all <=8 neighbor tiles must have published state i
        if (ntid >= 0) {
            while (g_flag[r][ntid] < cv) { }
        }
        __syncthreads();
        __threadfence();   // acquire: order halo loads after the flag observation

        // load phase: interior from regs, halo from L2; fill stage buffer 0
#pragma unroll
        for (int q = 0; q < NQ; ++q) {
            int mt = meta[q];
            sg[q] = 0.0f;
            ax_[q] = ay_[q] = az_[q] = 0.0f;
            if (mt & 8) {
                float vx, vy, vz;
                if (mt & 16) { vx = m0x[q]; vy = m0y[q]; vz = m0z[q]; }
                else {
                    float4 f = __ldcg(&g_fld[r][cur][ig[q]]);
                    vx = f.x; vy = f.y; vz = f.z;
                }
                m0x[q] = vx; m0y[q] = vy; m0z[q] = vz;
                sx_[q] = vx; sy_[q] = vy; sz_[q] = vz;
                sb4[tid + q * NT] = make_float4(vx, vy, vz, 0.0f);
                int sj = (mt >> 8) & 255;
                if (sj && run) sg[q] = __ldg(sgb + sj - 1);
            }
        }
        __syncthreads();

        // 4 RK4 stages in shared memory; active set shrinks by 1 ring/stage
        int p = 0;
        const float cst[3] = {0.5f, 0.5f, 1.0f};
        const float wst[4] = {1.0f, 2.0f, 2.0f, 1.0f};
#pragma unroll
        for (int st = 0; st < 4; ++st) {
            const float4* __restrict__ rb = sb4 + p * MAXC;
            float4* __restrict__ wb = sb4 + (p ^ 1) * MAXC;
#pragma unroll
            for (int q = 0; q < NQ; ++q) {
                if (st < (meta[q] & 7)) {
                    float4 nN = rb[nbN[q]];
                    float4 nS = rb[nbS[q]];
                    float4 nW = rb[nbW[q]];
                    float4 nE = rb[nbE[q]];

                    float lx = nN.x + nS.x + nW.x + nE.x - 4.0f * sx_[q];
                    float ly = nN.y + nS.y + nW.y + nE.y - 4.0f * sy_[q];
                    float lz = nN.z + nS.z + nW.z + nE.z - 4.0f * sz_[q];

                    float Bx = Bcx[q] + ce * lx;
                    float By = Bcy[q] + ce * ly;
                    float Bz = Bcz[q] + ce * lz + cd * sz_[q] + sg[q];

                    float cx = sy_[q] * Bz - sz_[q] * By;
                    float cy = sz_[q] * Bx - sx_[q] * Bz;
                    float cz = sx_[q] * By - sy_[q] * Bx;
                    float dx = sy_[q] * cz - sz_[q] * cy;
                    float dy = sz_[q] * cx - sx_[q] * cz;
                    float dz = sx_[q] * cy - sy_[q] * cx;
                    float ox = sy_[q] * sx_[q];
                    float oy = -(sz_[q] * sz_[q] + sx_[q] * sx_[q]);
                    float oz = sy_[q] * sz_[q];

                    float kx = -inv * (cx + alpha * dx) + C_SOT * ox;
                    float ky = -inv * (cy + alpha * dy) + C_SOT * oy;
                    float kz = -inv * (cz + alpha * dz) + C_SOT * oz;

                    ax_[q] += wst[st] * kx;
                    ay_[q] += wst[st] * ky;
                    az_[q] += wst[st] * kz;

                    if (st < 3) {
                        float cf = cst[st] * h;
                        sx_[q] = m0x[q] + cf * kx;
                        sy_[q] = m0y[q] + cf * ky;
                        sz_[q] = m0z[q] + cf * kz;
                        wb[tid + q * NT] = make_float4(sx_[q], sy_[q], sz_[q], 0.0f);
                    } else {
                        sx_[q] = m0x[q] + h6 * ax_[q];
                        sy_[q] = m0y[q] + h6 * ay_[q];
                        sz_[q] = m0z[q] + h6 * az_[q];
                    }
                }
            }
            if (st < 3) { __syncthreads(); p ^= 1; }
        }

        // store interior, capture relaxed z, emit probes
#pragma unroll
        for (int q = 0; q < NQ; ++q) {
            int mt = meta[q];
            if (mt & 16) {
                m0x[q] = sx_[q]; m0y[q] = sy_[q]; m0z[q] = sz_[q];
                g_fld[r][cur ^ 1][ig[q]] = make_float4(sx_[q], sy_[q], sz_[q], 0.0f);
                if (i == RELAX_STEPS - 1) mrelz[q] = sz_[q];
                int pj = (mt >> 16) & 255;
                if (pj && run) {
                    float v = finalb ? (sz_[q] - mrelz[q]) * Msat : sz_[q];
                    out[(r * TSTEPS + t) * NPROBE + pj - 1] = v;
                }
            }
        }

        // publish state i+1
        __syncthreads();
        if (tid == 0) {
            __threadfence();
            g_flag[r][tb] = cv + 1u;
        }
        ++cv;
        cur ^= 1;
    }
}

extern "C" void kernel_launch(void* const* d_in, const int* in_sizes, int n_in,
                              void* d_out, int out_size) {
    const float* list_signal = (const float*)d_in[0];
    const float* B_ext       = (const float*)d_in[1];
    const float* Msat        = (const float*)d_in[2];
    const int*   src_pos     = (const int*)d_in[3];
    const int*   probe_pos   = (const int*)d_in[4];
    const int*   final_board = (const int*)d_in[5];
    float*       out         = (float*)d_out;

    cudaFuncSetAttribute(mm_solver_kernel,
                         cudaFuncAttributeMaxDynamicSharedMemorySize, SMEM_BYTES);
    reset_kernel<<<1, 128>>>();
    mm_solver_kernel<<<NB, NT, SMEM_BYTES>>>(list_signal, B_ext, Msat, src_pos,
                                             probe_pos, final_board, out);
}

// round 11
// speedup vs baseline: 1.8053x; 1.8053x over previous
#include <cuda_runtime.h>

// ---------------------------------------------------------------------------
// Micromagnetic LLG solver (RK4, 5-pt exchange laplacian, SOT, demag-z).
// Round 10: TWO-STEP fusion (halo 8, 8 RK4 stages per grid sync).
//   - grid syncs 357 -> 179 (barrier ~2us/step was ~40% of step time)
//   - shrinking cone d <= 7-st keeps the interior bit-exact; cells d<=4
//     finalize step 1 at stage 3 and republish, interior finalizes at stage 7
//   - stages 0-3 use sig(t), stages 4-7 use sig(t+1); probes emitted at both
//   - B_ext per-cell constants in static smem (reg relief for NQ=5)
//   - proven round-7 central-counter barrier (64 single-lane arrivals/replica)
// ---------------------------------------------------------------------------

#define NXg 256
#define NYg 256
#define NCELL (NXg * NYg)
#define TSTEPS 256
#define NSRC 3
#define NPROBE 5
#define RELAX_STEPS 100

#define NB 128            // 2 replicas x 64 tiles, 1 CTA/SM, single wave
#define NT 512
#define HALO 8
#define EXT 48            // 32 + 2*8
#define MAXC (EXT * EXT)  // 2304
#define NQ 5
#define NSLOT (NQ * NT)   // 2560
#define SMEM_BYTES (2 * MAXC * (int)sizeof(float4))   // 73728
#define NFUSED ((RELAX_STEPS + TSTEPS) / 2)           // 178
#define RELAX_FUSED (RELAX_STEPS / 2)                 // 50

// [replica][parity][cell]
__device__ float4 g_fld[2][2][NCELL];
__device__ unsigned int g_cnt[2];
__device__ volatile unsigned int g_gen[2];

__global__ void reset_kernel() {
    if (threadIdx.x < 2) {
        g_cnt[threadIdx.x] = 0u;
        g_gen[threadIdx.x] = 0u;
    }
}

// Replica-local grid barrier: 64 single-lane arrivals on one counter,
// one-word generation poll by thread 0 only (proven round-7 pattern).
__device__ __forceinline__ void gbar(int r, unsigned int v) {
    __syncthreads();
    if (threadIdx.x == 0) {
        __threadfence();
        if (atomicAdd(&g_cnt[r], 1u) == 63u) {
            g_cnt[r] = 0u;
            __threadfence();
            g_gen[r] = v;
        } else {
            while (g_gen[r] < v) { }
        }
    }
    __syncthreads();
}

__global__ void __launch_bounds__(NT, 1)
mm_solver_kernel(const float* __restrict__ sigarr,   // [2, TSTEPS, NSRC]
                 const float* __restrict__ Bext,     // [1,3,NX,NY]
                 const float* __restrict__ msat,
                 const int*   __restrict__ srcp,     // [NSRC,2]
                 const int*   __restrict__ probep,   // [NPROBE,2]
                 const int*   __restrict__ fb,
                 float*       __restrict__ out)      // [2, TSTEPS, NPROBE]
{
    extern __shared__ float4 sb4[];        // [2][MAXC] ping-pong stage buffers
    __shared__ float4 bc_s[NSLOT];         // per-cell B_ext (persistent)

    const int tid = threadIdx.x;
    const int r  = blockIdx.x >> 6;        // replica = signal index
    const int tb = blockIdx.x & 63;
    const int tx = tb >> 3, ty = tb & 7;
    const int x0 = tx * 32, y0 = ty * 32;

    const float Msat = msat[0];
    const int finalb = fb[0];
    const float ce = (float)(2.0 * 3.5e-12 / ((double)Msat * (5e-8 * 5e-8)));
    const float cd = (float)(-(1.2566370614359172e-06) * (double)Msat);
    const float h  = (float)(175950000000.0 * 5e-12);
    const float h6 = (float)((175950000000.0 * 5e-12) / 6.0);
    const float C_SOT = 1.0e-4f;

    // meta bits: [0:4)=limp1 (stage st computed iff st < limp1), bit4=valid,
    //            bit5=interior, [8:16)=src idx+1, [16:24)=probe idx+1
    int meta[NQ], nbN[NQ], nbS[NQ], nbW[NQ], nbE[NQ], ig[NQ];
    float m0x[NQ], m0y[NQ], m0z[NQ];
    float mrelz[NQ];

#pragma unroll
    for (int q = 0; q < NQ; ++q) {
        int c  = tid + q * NT;
        int cc = (c < MAXC) ? c : 0;
        int sx = cc / EXT, sy = cc % EXT;
        int gx = x0 - HALO + sx, gy = y0 - HALO + sy;
        bool valid = (c < MAXC) && gx >= 0 && gx < NXg && gy >= 0 && gy < NYg;
        bool inter = valid && gx >= x0 && gx < x0 + 32 && gy >= y0 && gy < y0 + 32;
        // ring distance d = max outward distance from the 32x32 interior
        int dxn = (sx < HALO) ? (HALO - sx) : (sx >= HALO + 32 ? sx - (HALO + 31) : 0);
        int dyn = (sy < HALO) ? (HALO - sy) : (sy >= HALO + 32 ? sy - (HALO + 31) : 0);
        int d = dxn > dyn ? dxn : dyn;
        int limp1 = valid ? (8 - d) : 0;           // stages computed: st < limp1
        if (limp1 < 0) limp1 = 0;
        // neighbor clamp-to-self at physical edges (pad mode='edge'); ext-edge
        // clamps only ever feed rings outside the dependence cone
        nbN[q] = (sx > 0       && gx > 0      ) ? cc - EXT : cc;
        nbS[q] = (sx < EXT - 1 && gx < NXg - 1) ? cc + EXT : cc;
        nbW[q] = (sy > 0       && gy > 0      ) ? cc - 1   : cc;
        nbE[q] = (sy < EXT - 1 && gy < NYg - 1) ? cc + 1   : cc;
        int gxc = gx < 0 ? 0 : (gx > NXg - 1 ? NXg - 1 : gx);
        int gyc = gy < 0 ? 0 : (gy > NYg - 1 ? NYg - 1 : gy);
        int ign = gxc * NYg + gyc;
        ig[q] = ign;
        bc_s[c] = make_float4(Bext[ign], Bext[NCELL + ign], Bext[2 * NCELL + ign], 0.0f);
        int sj = 0, pj = 0;
        if (valid) {
#pragma unroll
            for (int k2 = 0; k2 < NSRC; ++k2)
                if (srcp[2 * k2] == gx && srcp[2 * k2 + 1] == gy) sj = k2 + 1;
            if (inter) {
#pragma unroll
                for (int k2 = 0; k2 < NPROBE; ++k2)
                    if (probep[2 * k2] == gx && probep[2 * k2 + 1] == gy) pj = k2 + 1;
            }
        }
        meta[q] = limp1 | (valid ? 16 : 0) | (inter ? 32 : 0) | (sj << 8) | (pj << 16);
        m0x[q] = 0.0f; m0y[q] = 1.0f; m0z[q] = 0.0f;
        mrelz[q] = 0.0f;
        if (inter) g_fld[r][0][ign] = make_float4(0.0f, 1.0f, 0.0f, 0.0f);
    }

    unsigned int gv = 0;
    int cur = 0;
    gbar(r, ++gv);

    float sx_[NQ], sy_[NQ], sz_[NQ], ax_[NQ], ay_[NQ], az_[NQ];
    float sgA[NQ], sgB[NQ];

    // ---- fused step loop: 50 relax pairs + 128 run pairs ----
#pragma unroll 1
    for (int i = 0; i < NFUSED; ++i) {
        const bool run = (i >= RELAX_FUSED);
        const int  tA  = 2 * i - RELAX_STEPS;       // first half-step time idx
        const float alpha = run ? 0.01f : 0.5f;
        const float inv   = run ? (1.0f / (1.0f + 0.01f * 0.01f))
                                : (1.0f / (1.0f + 0.5f * 0.5f));
        const float* sgb = sigarr + (r * TSTEPS + (run ? tA : 0)) * NSRC;

        // load phase: interior from regs, halo from L2; fill stage buffer 0
#pragma unroll
        for (int q = 0; q < NQ; ++q) {
            int mt = meta[q];
            sgA[q] = 0.0f; sgB[q] = 0.0f;
            ax_[q] = ay_[q] = az_[q] = 0.0f;
            if (mt & 16) {
                float vx, vy, vz;
                if (mt & 32) { vx = m0x[q]; vy = m0y[q]; vz = m0z[q]; }
                else {
                    float4 f = __ldcg(&g_fld[r][cur][ig[q]]);
                    vx = f.x; vy = f.y; vz = f.z;
                }
                m0x[q] = vx; m0y[q] = vy; m0z[q] = vz;
                sx_[q] = vx; sy_[q] = vy; sz_[q] = vz;
                sb4[tid + q * NT] = make_float4(vx, vy, vz, 0.0f);
                int sj = (mt >> 8) & 255;
                if (sj && run) {
                    sgA[q] = __ldg(sgb + sj - 1);
                    sgB[q] = __ldg(sgb + NSRC + sj - 1);
                }
            }
        }
        __syncthreads();

        // 8 RK4 stages (2 full steps) in shared memory; cone shrinks 1/stage
        int p = 0;
#pragma unroll
        for (int st = 0; st < 8; ++st) {
            const int k = st & 3;                  // stage index within step
            const float wk = (k == 1 || k == 2) ? 2.0f : 1.0f;
            const float ck = (k == 2) ? 1.0f : 0.5f;
            const float4* __restrict__ rb = sb4 + p * MAXC;
            float4* __restrict__ wb = sb4 + (p ^ 1) * MAXC;
#pragma unroll
            for (int q = 0; q < NQ; ++q) {
                if (st < (meta[q] & 15)) {
                    int c = tid + q * NT;
                    float4 nN = rb[nbN[q]];
                    float4 nS = rb[nbS[q]];
                    float4 nW = rb[nbW[q]];
                    float4 nE = rb[nbE[q]];
                    float4 bc = bc_s[c];
                    float sigv = (st < 4) ? sgA[q] : sgB[q];

                    float lx = nN.x + nS.x + nW.x + nE.x - 4.0f * sx_[q];
                    float ly = nN.y + nS.y + nW.y + nE.y - 4.0f * sy_[q];
                    float lz = nN.z + nS.z + nW.z + nE.z - 4.0f * sz_[q];

                    float Bx = bc.x + ce * lx;
                    float By = bc.y + ce * ly;
                    float Bz = bc.z + ce * lz + cd * sz_[q] + sigv;

                    float cx = sy_[q] * Bz - sz_[q] * By;
                    float cy = sz_[q] * Bx - sx_[q] * Bz;
                    float cz = sx_[q] * By - sy_[q] * Bx;
                    float dx = sy_[q] * cz - sz_[q] * cy;
                    float dy = sz_[q] * cx - sx_[q] * cz;
                    float dz = sx_[q] * cy - sy_[q] * cx;
                    float ox = sy_[q] * sx_[q];
                    float oy = -(sz_[q] * sz_[q] + sx_[q] * sx_[q]);
                    float oz = sy_[q] * sz_[q];

                    float kx = -inv * (cx + alpha * dx) + C_SOT * ox;
                    float ky = -inv * (cy + alpha * dy) + C_SOT * oy;
                    float kz = -inv * (cz + alpha * dz) + C_SOT * oz;

                    ax_[q] += wk * kx;
                    ay_[q] += wk * ky;
                    az_[q] += wk * kz;

                    if (k < 3) {
                        float cf = ck * h;
                        sx_[q] = m0x[q] + cf * kx;
                        sy_[q] = m0y[q] + cf * ky;
                        sz_[q] = m0z[q] + cf * kz;
                    } else {
                        // finalize this half-step's m; republish for stage 4+
                        sx_[q] = m0x[q] + h6 * ax_[q];
                        sy_[q] = m0y[q] + h6 * ay_[q];
                        sz_[q] = m0z[q] + h6 * az_[q];
                        m0x[q] = sx_[q]; m0y[q] = sy_[q]; m0z[q] = sz_[q];
                        ax_[q] = 0.0f; ay_[q] = 0.0f; az_[q] = 0.0f;
                        // probe emission for the first half-step (t = tA)
                        if (st == 3) {
                            int pj = (meta[q] >> 16) & 255;
                            if (pj && run) {
                                float v = finalb ? (sz_[q] - mrelz[q]) * Msat : sz_[q];
                                out[(r * TSTEPS + tA) * NPROBE + pj - 1] = v;
                            }
                        }
                    }
                    if (st < 7)
                        wb[c] = make_float4(sx_[q], sy_[q], sz_[q], 0.0f);
                }
            }
            if (st < 7) { __syncthreads(); p ^= 1; }
        }

        // store interior, capture relaxed z, emit second-half probes (t = tA+1)
#pragma unroll
        for (int q = 0; q < NQ; ++q) {
            int mt = meta[q];
            if (mt & 32) {
                g_fld[r][cur ^ 1][ig[q]] = make_float4(m0x[q], m0y[q], m0z[q], 0.0f);
                if (i == RELAX_FUSED - 1) mrelz[q] = m0z[q];
                int pj = (mt >> 16) & 255;
                if (pj && run) {
                    float v = finalb ? (m0z[q] - mrelz[q]) * Msat : m0z[q];
                    out[(r * TSTEPS + tA + 1) * NPROBE + pj - 1] = v;
                }
            }
        }
        cur ^= 1;
        gbar(r, ++gv);
    }
}

extern "C" void kernel_launch(void* const* d_in, const int* in_sizes, int n_in,
                              void* d_out, int out_size) {
    const float* list_signal = (const float*)d_in[0];
    const float* B_ext       = (const float*)d_in[1];
    const float* Msat        = (const float*)d_in[2];
    const int*   src_pos     = (const int*)d_in[3];
    const int*   probe_pos   = (const int*)d_in[4];
    const int*   final_board = (const int*)d_in[5];
    float*       out         = (float*)d_out;

    cudaFuncSetAttribute(mm_solver_kernel,
                         cudaFuncAttributeMaxDynamicSharedMemorySize, SMEM_BYTES);
    reset_kernel<<<1, 32>>>();
    mm_solver_kernel<<<NB, NT, SMEM_BYTES>>>(list_signal, B_ext, Msat, src_pos,
                                             probe_pos, final_board, out);
}

// round 12
// speedup vs baseline: 1.8986x; 1.0517x over previous
#include <cuda_runtime.h>

// ---------------------------------------------------------------------------
// Micromagnetic LLG solver (RK4, 5-pt exchange laplacian, SOT, demag-z).
// Round 11: register-resident N/S stencil direction.
//   - thread = vertical 3-cell column segment (16 segs x 48 cols = 768 thr)
//   - N/S of inner cells from registers (rolling prev-stage copy); only
//     segment-boundary N/S (2 per 3 cells) + W/E from smem
//   - LDS bytes per cell-stage 96 -> 59 (L1 was the binding resource at 47%)
//   - B_ext per-cell constants back in registers (bc smem read removed)
//   - physical x-edge clamp via mirror-register fixup (pad=edge exact)
//   - keeps: two-step fusion (halo 8, 8 stages/sync), 2 replicas, shrinking
//     cone, float4 smem ping-pong, round-7 central-counter barrier
// ---------------------------------------------------------------------------

#define NXg 256
#define NYg 256
#define NCELL (NXg * NYg)
#define TSTEPS 256
#define NSRC 3
#define NPROBE 5
#define RELAX_STEPS 100

#define NB 128            // 2 replicas x 64 tiles, 1 CTA/SM, single wave
#define NT 768            // 16 segments x 48 columns
#define NSEG 16
#define NQ 3              // cells per thread (vertical)
#define HALO 8
#define EXT 48            // 32 + 2*8
#define MAXC (EXT * EXT)  // 2304 = 768*3
#define SMEM_BYTES (2 * MAXC * (int)sizeof(float4))   // 73728
#define NFUSED ((RELAX_STEPS + TSTEPS) / 2)           // 178
#define RELAX_FUSED (RELAX_STEPS / 2)                 // 50

// [replica][parity][cell]
__device__ float4 g_fld[2][2][NCELL];
__device__ unsigned int g_cnt[2];
__device__ volatile unsigned int g_gen[2];

__global__ void reset_kernel() {
    if (threadIdx.x < 2) {
        g_cnt[threadIdx.x] = 0u;
        g_gen[threadIdx.x] = 0u;
    }
}

// Replica-local grid barrier: 64 single-lane arrivals on one counter,
// one-word generation poll by thread 0 only (proven round-7 pattern).
__device__ __forceinline__ void gbar(int r, unsigned int v) {
    __syncthreads();
    if (threadIdx.x == 0) {
        __threadfence();
        if (atomicAdd(&g_cnt[r], 1u) == 63u) {
            g_cnt[r] = 0u;
            __threadfence();
            g_gen[r] = v;
        } else {
            while (g_gen[r] < v) { }
        }
    }
    __syncthreads();
}

__global__ void __launch_bounds__(NT, 1)
mm_solver_kernel(const float* __restrict__ sigarr,   // [2, TSTEPS, NSRC]
                 const float* __restrict__ Bext,     // [1,3,NX,NY]
                 const float* __restrict__ msat,
                 const int*   __restrict__ srcp,     // [NSRC,2]
                 const int*   __restrict__ probep,   // [NPROBE,2]
                 const int*   __restrict__ fb,
                 float*       __restrict__ out)      // [2, TSTEPS, NPROBE]
{
    extern __shared__ float4 sb4[];        // [2][MAXC] ping-pong stage buffers

    const int tid = threadIdx.x;
    const int r  = blockIdx.x >> 6;        // replica = signal index
    const int tb = blockIdx.x & 63;
    const int tx = tb >> 3, ty = tb & 7;
    const int x0 = tx * 32, y0 = ty * 32;

    const int seg = tid / EXT;             // 0..15
    const int sy  = tid - seg * EXT;       // 0..47
    const int gy  = y0 - HALO + sy;
    const int c0  = seg * NQ * EXT + sy;   // smem index of q=0 cell
    const int offW = (sy > 0 && gy > 0) ? -1 : 0;            // W/E clamp (y)
    const int offE = (sy < EXT - 1 && gy < NYg - 1) ? 1 : 0;
    const int nIdx = (seg > 0) ? c0 - EXT : c0;              // q=0 N boundary
    const int sIdx = (seg < NSEG - 1) ? c0 + 3 * EXT : c0 + 2 * EXT; // q=2 S

    // mirror-register fixup for physical x-edge clamp (rows gx=0 / gx=255
    // land mid-segment only in x0==0 seg==2 / x0==224 seg==13 tiles)
    bool mfix = false; int mi = 2;
    if (x0 == 0 && seg == 2)    { mfix = true; mi = 2; }
    if (x0 == 224 && seg == 13) { mfix = true; mi = 0; }

    const float Msat = msat[0];
    const int finalb = fb[0];
    const float ce = (float)(2.0 * 3.5e-12 / ((double)Msat * (5e-8 * 5e-8)));
    const float cd = (float)(-(1.2566370614359172e-06) * (double)Msat);
    const float h  = (float)(175950000000.0 * 5e-12);
    const float h6 = (float)((175950000000.0 * 5e-12) / 6.0);
    const float C_SOT = 1.0e-4f;

    // meta bits: [0:4)=limp1 (stage st computed iff st < limp1), bit4=valid,
    //            bit5=interior, [8:16)=src idx+1, [16:24)=probe idx+1
    int meta[NQ], ig[NQ];
    float bcx[NQ], bcy[NQ], bcz[NQ];
    float m0x[NQ], m0y[NQ], m0z[NQ];
    float sx_[NQ], sy_[NQ], sz_[NQ];
    float mrelz[NQ];

#pragma unroll
    for (int q = 0; q < NQ; ++q) {
        int sx = NQ * seg + q;                 // 0..47
        int gx = x0 - HALO + sx;
        bool valid = gx >= 0 && gx < NXg && gy >= 0 && gy < NYg;
        bool inter = valid && gx >= x0 && gx < x0 + 32 && gy >= y0 && gy < y0 + 32;
        int dxn = (sx < HALO) ? (HALO - sx) : (sx >= HALO + 32 ? sx - (HALO + 31) : 0);
        int dyn = (sy < HALO) ? (HALO - sy) : (sy >= HALO + 32 ? sy - (HALO + 31) : 0);
        int d = dxn > dyn ? dxn : dyn;
        int limp1 = valid ? (8 - d) : 0;
        if (limp1 < 0) limp1 = 0;
        int gxc = gx < 0 ? 0 : (gx > NXg - 1 ? NXg - 1 : gx);
        int gyc = gy < 0 ? 0 : (gy > NYg - 1 ? NYg - 1 : gy);
        int ign = gxc * NYg + gyc;
        ig[q] = ign;
        bcx[q] = Bext[ign];
        bcy[q] = Bext[NCELL + ign];
        bcz[q] = Bext[2 * NCELL + ign];
        int sj = 0, pj = 0;
        if (valid) {
#pragma unroll
            for (int k2 = 0; k2 < NSRC; ++k2)
                if (srcp[2 * k2] == gx && srcp[2 * k2 + 1] == gy) sj = k2 + 1;
            if (inter) {
#pragma unroll
                for (int k2 = 0; k2 < NPROBE; ++k2)
                    if (probep[2 * k2] == gx && probep[2 * k2 + 1] == gy) pj = k2 + 1;
            }
        }
        meta[q] = limp1 | (valid ? 16 : 0) | (inter ? 32 : 0) | (sj << 8) | (pj << 16);
        m0x[q] = 0.0f; m0y[q] = 1.0f; m0z[q] = 0.0f;
        sx_[q] = 0.0f; sy_[q] = 1.0f; sz_[q] = 0.0f;
        mrelz[q] = 0.0f;
        if (inter) g_fld[r][0][ign] = make_float4(0.0f, 1.0f, 0.0f, 0.0f);
    }

    unsigned int gv = 0;
    int cur = 0;
    gbar(r, ++gv);

    float ax_[NQ], ay_[NQ], az_[NQ];
    float sgA[NQ], sgB[NQ];

    // ---- fused step loop: 50 relax pairs + 128 run pairs ----
#pragma unroll 1
    for (int i = 0; i < NFUSED; ++i) {
        const bool run = (i >= RELAX_FUSED);
        const int  tA  = 2 * i - RELAX_STEPS;       // first half-step time idx
        const float alpha = run ? 0.01f : 0.5f;
        const float inv   = run ? (1.0f / (1.0f + 0.01f * 0.01f))
                                : (1.0f / (1.0f + 0.5f * 0.5f));
        const float* sgb = sigarr + (r * TSTEPS + (run ? tA : 0)) * NSRC;

        // load phase: interior from regs, halo from L2; fill stage buffer 0
#pragma unroll
        for (int q = 0; q < NQ; ++q) {
            int mt = meta[q];
            sgA[q] = 0.0f; sgB[q] = 0.0f;
            ax_[q] = ay_[q] = az_[q] = 0.0f;
            if (mt & 16) {
                float vx, vy, vz;
                if (mt & 32) { vx = m0x[q]; vy = m0y[q]; vz = m0z[q]; }
                else {
                    float4 f = __ldcg(&g_fld[r][cur][ig[q]]);
                    vx = f.x; vy = f.y; vz = f.z;
                }
                m0x[q] = vx; m0y[q] = vy; m0z[q] = vz;
                sx_[q] = vx; sy_[q] = vy; sz_[q] = vz;
                sb4[c0 + q * EXT] = make_float4(vx, vy, vz, 0.0f);
                int sj = (mt >> 8) & 255;
                if (sj && run) {
                    sgA[q] = __ldg(sgb + sj - 1);
                    sgB[q] = __ldg(sgb + NSRC + sj - 1);
                }
            }
        }
        __syncthreads();

        // 8 RK4 stages (2 full steps); N/S from registers, W/E+bounds from smem
        int p = 0;
#pragma unroll
        for (int st = 0; st < 8; ++st) {
            const int k = st & 3;                  // stage index within step
            const float wk = (k == 1 || k == 2) ? 2.0f : 1.0f;
            const float ck = (k == 2) ? 1.0f : 0.5f;
            const float4* __restrict__ rb = sb4 + p * MAXC;
            float4* __restrict__ wb = sb4 + (p ^ 1) * MAXC;
            float px = 0.0f, py = 0.0f, pz = 0.0f;   // prev-stage value of q-1
#pragma unroll
            for (int q = 0; q < NQ; ++q) {
                const float ox = sx_[q], oy = sy_[q], oz = sz_[q];
                if (st < (meta[q] & 15)) {
                    const int cq = c0 + q * EXT;
                    float4 nW = rb[cq + offW];
                    float4 nE = rb[cq + offE];
                    float Nx, Ny, Nz, Sx, Sy, Sz;
                    if (q == 0) { float4 t = rb[nIdx]; Nx = t.x; Ny = t.y; Nz = t.z; }
                    else        { Nx = px; Ny = py; Nz = pz; }
                    if (q == NQ - 1) { float4 t = rb[sIdx]; Sx = t.x; Sy = t.y; Sz = t.z; }
                    else             { Sx = sx_[q + 1]; Sy = sy_[q + 1]; Sz = sz_[q + 1]; }
                    float sigv = (st < 4) ? sgA[q] : sgB[q];

                    float lx = Nx + Sx + nW.x + nE.x - 4.0f * ox;
                    float ly = Ny + Sy + nW.y + nE.y - 4.0f * oy;
                    float lz = Nz + Sz + nW.z + nE.z - 4.0f * oz;

                    float Bx = bcx[q] + ce * lx;
                    float By = bcy[q] + ce * ly;
                    float Bz = bcz[q] + ce * lz + cd * oz + sigv;

                    float cx = oy * Bz - oz * By;
                    float cy = oz * Bx - ox * Bz;
                    float cz = ox * By - oy * Bx;
                    float dx = oy * cz - oz * cy;
                    float dy = oz * cx - ox * cz;
                    float dz = ox * cy - oy * cx;
                    float qx = oy * ox;
                    float qy = -(oz * oz + ox * ox);
                    float qz = oy * oz;

                    float kx = -inv * (cx + alpha * dx) + C_SOT * qx;
                    float ky = -inv * (cy + alpha * dy) + C_SOT * qy;
                    float kz = -inv * (cz + alpha * dz) + C_SOT * qz;

                    ax_[q] += wk * kx;
                    ay_[q] += wk * ky;
                    az_[q] += wk * kz;

                    if (k < 3) {
                        float cf = ck * h;
                        sx_[q] = m0x[q] + cf * kx;
                        sy_[q] = m0y[q] + cf * ky;
                        sz_[q] = m0z[q] + cf * kz;
                    } else {
                        sx_[q] = m0x[q] + h6 * ax_[q];
                        sy_[q] = m0y[q] + h6 * ay_[q];
                        sz_[q] = m0z[q] + h6 * az_[q];
                        m0x[q] = sx_[q]; m0y[q] = sy_[q]; m0z[q] = sz_[q];
                        ax_[q] = 0.0f; ay_[q] = 0.0f; az_[q] = 0.0f;
                        if (st == 3) {
                            int pj = (meta[q] >> 16) & 255;
                            if (pj && run) {
                                float v = finalb ? (sz_[q] - mrelz[q]) * Msat : sz_[q];
                                out[(r * TSTEPS + tA) * NPROBE + pj - 1] = v;
                            }
                        }
                    }
                    if (st < 7)
                        wb[cq] = make_float4(sx_[q], sy_[q], sz_[q], 0.0f);
                }
                px = ox; py = oy; pz = oz;
            }
            // physical x-edge clamp: mirror cell tracks its edge neighbor
            if (mfix) { sx_[1] = sx_[mi]; sy_[1] = sy_[mi]; sz_[1] = sz_[mi]; }
            if (st < 7) { __syncthreads(); p ^= 1; }
        }

        // store interior, capture relaxed z, emit second-half probes (t = tA+1)
#pragma unroll
        for (int q = 0; q < NQ; ++q) {
            int mt = meta[q];
            if (mt & 32) {
                g_fld[r][cur ^ 1][ig[q]] = make_float4(m0x[q], m0y[q], m0z[q], 0.0f);
                if (i == RELAX_FUSED - 1) mrelz[q] = m0z[q];
                int pj = (mt >> 16) & 255;
                if (pj && run) {
                    float v = finalb ? (m0z[q] - mrelz[q]) * Msat : m0z[q];
                    out[(r * TSTEPS + tA + 1) * NPROBE + pj - 1] = v;
                }
            }
        }
        cur ^= 1;
        gbar(r, ++gv);
    }
}

extern "C" void kernel_launch(void* const* d_in, const int* in_sizes, int n_in,
                              void* d_out, int out_size) {
    const float* list_signal = (const float*)d_in[0];
    const float* B_ext       = (const float*)d_in[1];
    const float* Msat        = (const float*)d_in[2];
    const int*   src_pos     = (const int*)d_in[3];
    const int*   probe_pos   = (const int*)d_in[4];
    const int*   final_board = (const int*)d_in[5];
    float*       out         = (float*)d_out;

    cudaFuncSetAttribute(mm_solver_kernel,
                         cudaFuncAttributeMaxDynamicSharedMemorySize, SMEM_BYTES);
    reset_kernel<<<1, 32>>>();
    mm_solver_kernel<<<NB, NT, SMEM_BYTES>>>(list_signal, B_ext, Msat, src_pos,
                                             probe_pos, final_board, out);
}

// round 13
// speedup vs baseline: 2.1213x; 1.1173x over previous
#include <cuda_runtime.h>

// ---------------------------------------------------------------------------
// Micromagnetic LLG solver (RK4, 5-pt exchange laplacian, SOT, demag-z).
// Round 12: split-phase grid barrier + ALU-slot trim.
//   - arrive (atomicAdd) immediately after interior publish; the interior
//     smem staging + signal loads for the NEXT pair run between arrive and
//     wait, overlapping the ~2us barrier RTT with useful work
//   - meta decoded once into registers (lim/inter/sj/pj): no bitfield
//     extraction in the 8-stage hot loop
//   - otherwise round-11 structure: vertical 3-cell segments (768 thr),
//     register-resident N/S, two-step fusion (halo 8), 2 replicas,
//     shrinking cone, float4 smem ping-pong, central-counter barrier
// ---------------------------------------------------------------------------

#define NXg 256
#define NYg 256
#define NCELL (NXg * NYg)
#define TSTEPS 256
#define NSRC 3
#define NPROBE 5
#define RELAX_STEPS 100

#define NB 128            // 2 replicas x 64 tiles, 1 CTA/SM, single wave
#define NT 768            // 16 segments x 48 columns
#define NSEG 16
#define NQ 3              // cells per thread (vertical)
#define HALO 8
#define EXT 48            // 32 + 2*8
#define MAXC (EXT * EXT)  // 2304 = 768*3
#define SMEM_BYTES (2 * MAXC * (int)sizeof(float4))   // 73728
#define NFUSED ((RELAX_STEPS + TSTEPS) / 2)           // 178
#define RELAX_FUSED (RELAX_STEPS / 2)                 // 50

// [replica][parity][cell]
__device__ float4 g_fld[2][2][NCELL];
__device__ unsigned int g_cnt[2];
__device__ volatile unsigned int g_gen[2];

__global__ void reset_kernel() {
    if (threadIdx.x < 2) {
        g_cnt[threadIdx.x] = 0u;
        g_gen[threadIdx.x] = 0u;
    }
}

// Arrival half of the split barrier: 64 single-lane arrivals on one counter.
// Winner resets the counter and publishes the generation.
__device__ __forceinline__ void gbar_arrive(int r, unsigned int v) {
    if (atomicAdd(&g_cnt[r], 1u) == 63u) {
        g_cnt[r] = 0u;
        __threadfence();
        g_gen[r] = v;
    }
}

__global__ void __launch_bounds__(NT, 1)
mm_solver_kernel(const float* __restrict__ sigarr,   // [2, TSTEPS, NSRC]
                 const float* __restrict__ Bext,     // [1,3,NX,NY]
                 const float* __restrict__ msat,
                 const int*   __restrict__ srcp,     // [NSRC,2]
                 const int*   __restrict__ probep,   // [NPROBE,2]
                 const int*   __restrict__ fb,
                 float*       __restrict__ out)      // [2, TSTEPS, NPROBE]
{
    extern __shared__ float4 sb4[];        // [2][MAXC] ping-pong stage buffers

    const int tid = threadIdx.x;
    const int r  = blockIdx.x >> 6;        // replica = signal index
    const int tb = blockIdx.x & 63;
    const int tx = tb >> 3, ty = tb & 7;
    const int x0 = tx * 32, y0 = ty * 32;

    const int seg = tid / EXT;             // 0..15
    const int sy  = tid - seg * EXT;       // 0..47
    const int gy  = y0 - HALO + sy;
    const int c0  = seg * NQ * EXT + sy;   // smem index of q=0 cell
    const int offW = (sy > 0 && gy > 0) ? -1 : 0;            // W/E clamp (y)
    const int offE = (sy < EXT - 1 && gy < NYg - 1) ? 1 : 0;
    const int nIdx = (seg > 0) ? c0 - EXT : c0;              // q=0 N boundary
    const int sIdx = (seg < NSEG - 1) ? c0 + 3 * EXT : c0 + 2 * EXT; // q=2 S

    // mirror-register fixup for physical x-edge clamp (rows gx=0 / gx=255
    // land mid-segment only in x0==0 seg==2 / x0==224 seg==13 tiles)
    bool mfix = false; int mi = 2;
    if (x0 == 0 && seg == 2)    { mfix = true; mi = 2; }
    if (x0 == 224 && seg == 13) { mfix = true; mi = 0; }

    const float Msat = msat[0];
    const int finalb = fb[0];
    const float ce = (float)(2.0 * 3.5e-12 / ((double)Msat * (5e-8 * 5e-8)));
    const float cd = (float)(-(1.2566370614359172e-06) * (double)Msat);
    const float h  = (float)(175950000000.0 * 5e-12);
    const float h6 = (float)((175950000000.0 * 5e-12) / 6.0);
    const float C_SOT = 1.0e-4f;

    // decoded per-cell state (no bitfield extraction in the hot loop)
    int lim[NQ], sjr[NQ], pjr[NQ], ig[NQ];
    bool inter[NQ];
    float bcx[NQ], bcy[NQ], bcz[NQ];
    float m0x[NQ], m0y[NQ], m0z[NQ];
    float sx_[NQ], sy_[NQ], sz_[NQ];
    float mrelz[NQ];

#pragma unroll
    for (int q = 0; q < NQ; ++q) {
        int sx = NQ * seg + q;                 // 0..47
        int gx = x0 - HALO + sx;
        bool valid = gx >= 0 && gx < NXg && gy >= 0 && gy < NYg;
        inter[q] = valid && gx >= x0 && gx < x0 + 32 && gy >= y0 && gy < y0 + 32;
        int dxn = (sx < HALO) ? (HALO - sx) : (sx >= HALO + 32 ? sx - (HALO + 31) : 0);
        int dyn = (sy < HALO) ? (HALO - sy) : (sy >= HALO + 32 ? sy - (HALO + 31) : 0);
        int d = dxn > dyn ? dxn : dyn;
        lim[q] = valid ? (8 - d) : 0;
        if (lim[q] < 0) lim[q] = 0;
        int gxc = gx < 0 ? 0 : (gx > NXg - 1 ? NXg - 1 : gx);
        int gyc = gy < 0 ? 0 : (gy > NYg - 1 ? NYg - 1 : gy);
        int ign = gxc * NYg + gyc;
        ig[q] = ign;
        bcx[q] = Bext[ign];
        bcy[q] = Bext[NCELL + ign];
        bcz[q] = Bext[2 * NCELL + ign];
        sjr[q] = 0; pjr[q] = 0;
        if (valid) {
#pragma unroll
            for (int k2 = 0; k2 < NSRC; ++k2)
                if (srcp[2 * k2] == gx && srcp[2 * k2 + 1] == gy) sjr[q] = k2 + 1;
            if (inter[q]) {
#pragma unroll
                for (int k2 = 0; k2 < NPROBE; ++k2)
                    if (probep[2 * k2] == gx && probep[2 * k2 + 1] == gy) pjr[q] = k2 + 1;
            }
        }
        m0x[q] = 0.0f; m0y[q] = 1.0f; m0z[q] = 0.0f;
        sx_[q] = 0.0f; sy_[q] = 1.0f; sz_[q] = 0.0f;
        mrelz[q] = 0.0f;
        if (inter[q]) g_fld[r][0][ign] = make_float4(0.0f, 1.0f, 0.0f, 0.0f);
    }

    // initial publish + arrive (instance 1)
    __syncthreads();
    if (tid == 0) {
        __threadfence();
        gbar_arrive(r, 1u);
    }
    unsigned int gv = 1;
    int cur = 0;

    float ax_[NQ], ay_[NQ], az_[NQ];
    float sgA[NQ], sgB[NQ];

    // ---- fused step loop: 50 relax pairs + 128 run pairs ----
#pragma unroll 1
    for (int i = 0; i < NFUSED; ++i) {
        const bool run = (i >= RELAX_FUSED);
        const int  tA  = 2 * i - RELAX_STEPS;       // first half-step time idx
        const float alpha = run ? 0.01f : 0.5f;
        const float inv   = run ? (1.0f / (1.0f + 0.01f * 0.01f))
                                : (1.0f / (1.0f + 0.5f * 0.5f));
        const float* sgb = sigarr + (r * TSTEPS + (run ? tA : 0)) * NSRC;

        // Phase A (between arrive and wait — no neighbor dependency):
        // publish register-resident interior to stage buffer 0, reset
        // accumulators, load signal values.
#pragma unroll
        for (int q = 0; q < NQ; ++q) {
            sgA[q] = 0.0f; sgB[q] = 0.0f;
            ax_[q] = ay_[q] = az_[q] = 0.0f;
            if (inter[q]) {
                sx_[q] = m0x[q]; sy_[q] = m0y[q]; sz_[q] = m0z[q];
                sb4[c0 + q * EXT] = make_float4(m0x[q], m0y[q], m0z[q], 0.0f);
            }
            if (sjr[q] && run) {
                sgA[q] = __ldg(sgb + sjr[q] - 1);
                sgB[q] = __ldg(sgb + NSRC + sjr[q] - 1);
            }
        }

        // Wait half of the split barrier.
        if (tid == 0) {
            while (g_gen[r] < gv) { }
        }
        __syncthreads();
        __threadfence();   // acquire: order halo loads after the observation

        // Phase B: halo cells from L2.
#pragma unroll
        for (int q = 0; q < NQ; ++q) {
            if (lim[q] > 0 && !inter[q]) {
                float4 f = __ldcg(&g_fld[r][cur][ig[q]]);
                m0x[q] = f.x; m0y[q] = f.y; m0z[q] = f.z;
                sx_[q] = f.x; sy_[q] = f.y; sz_[q] = f.z;
                sb4[c0 + q * EXT] = make_float4(f.x, f.y, f.z, 0.0f);
            }
        }
        __syncthreads();

        // 8 RK4 stages (2 full steps); N/S from registers, W/E+bounds from smem
        int p = 0;
#pragma unroll
        for (int st = 0; st < 8; ++st) {
            const int k = st & 3;                  // stage index within step
            const float wk = (k == 1 || k == 2) ? 2.0f : 1.0f;
            const float ck = (k == 2) ? 1.0f : 0.5f;
            const float4* __restrict__ rb = sb4 + p * MAXC;
            float4* __restrict__ wb = sb4 + (p ^ 1) * MAXC;
            float px = 0.0f, py = 0.0f, pz = 0.0f;   // prev-stage value of q-1
#pragma unroll
            for (int q = 0; q < NQ; ++q) {
                const float ox = sx_[q], oy = sy_[q], oz = sz_[q];
                if (st < lim[q]) {
                    const int cq = c0 + q * EXT;
                    float4 nW = rb[cq + offW];
                    float4 nE = rb[cq + offE];
                    float Nx, Ny, Nz, Sx, Sy, Sz;
                    if (q == 0) { float4 t = rb[nIdx]; Nx = t.x; Ny = t.y; Nz = t.z; }
                    else        { Nx = px; Ny = py; Nz = pz; }
                    if (q == NQ - 1) { float4 t = rb[sIdx]; Sx = t.x; Sy = t.y; Sz = t.z; }
                    else             { Sx = sx_[q + 1]; Sy = sy_[q + 1]; Sz = sz_[q + 1]; }
                    float sigv = (st < 4) ? sgA[q] : sgB[q];

                    float lx = Nx + Sx + nW.x + nE.x - 4.0f * ox;
                    float ly = Ny + Sy + nW.y + nE.y - 4.0f * oy;
                    float lz = Nz + Sz + nW.z + nE.z - 4.0f * oz;

                    float Bx = bcx[q] + ce * lx;
                    float By = bcy[q] + ce * ly;
                    float Bz = bcz[q] + ce * lz + cd * oz + sigv;

                    float cx = oy * Bz - oz * By;
                    float cy = oz * Bx - ox * Bz;
                    float cz = ox * By - oy * Bx;
                    float dx = oy * cz - oz * cy;
                    float dy = oz * cx - ox * cz;
                    float dz = ox * cy - oy * cx;
                    float qx = oy * ox;
                    float qy = -(oz * oz + ox * ox);
                    float qz = oy * oz;

                    float kx = -inv * (cx + alpha * dx) + C_SOT * qx;
                    float ky = -inv * (cy + alpha * dy) + C_SOT * qy;
                    float kz = -inv * (cz + alpha * dz) + C_SOT * qz;

                    ax_[q] += wk * kx;
                    ay_[q] += wk * ky;
                    az_[q] += wk * kz;

                    if (k < 3) {
                        float cf = ck * h;
                        sx_[q] = m0x[q] + cf * kx;
                        sy_[q] = m0y[q] + cf * ky;
                        sz_[q] = m0z[q] + cf * kz;
                    } else {
                        sx_[q] = m0x[q] + h6 * ax_[q];
                        sy_[q] = m0y[q] + h6 * ay_[q];
                        sz_[q] = m0z[q] + h6 * az_[q];
                        m0x[q] = sx_[q]; m0y[q] = sy_[q]; m0z[q] = sz_[q];
                        ax_[q] = 0.0f; ay_[q] = 0.0f; az_[q] = 0.0f;
                        if (st == 3) {
                            if (pjr[q] && run) {
                                float v = finalb ? (sz_[q] - mrelz[q]) * Msat : sz_[q];
                                out[(r * TSTEPS + tA) * NPROBE + pjr[q] - 1] = v;
                            }
                        }
                    }
                    if (st < 7)
                        wb[cq] = make_float4(sx_[q], sy_[q], sz_[q], 0.0f);
                }
                px = ox; py = oy; pz = oz;
            }
            // physical x-edge clamp: mirror cell tracks its edge neighbor
            if (mfix) { sx_[1] = sx_[mi]; sy_[1] = sy_[mi]; sz_[1] = sz_[mi]; }
            if (st < 7) { __syncthreads(); p ^= 1; }
        }

        // store interior, capture relaxed z, emit second-half probes (t = tA+1)
#pragma unroll
        for (int q = 0; q < NQ; ++q) {
            if (inter[q]) {
                g_fld[r][cur ^ 1][ig[q]] = make_float4(m0x[q], m0y[q], m0z[q], 0.0f);
                if (i == RELAX_FUSED - 1) mrelz[q] = m0z[q];
                if (pjr[q] && run) {
                    float v = finalb ? (m0z[q] - mrelz[q]) * Msat : m0z[q];
                    out[(r * TSTEPS + tA + 1) * NPROBE + pjr[q] - 1] = v;
                }
            }
        }

        // arrive for the next barrier instance; wait happens next iteration
        __syncthreads();
        if (tid == 0) {
            __threadfence();
            gbar_arrive(r, gv + 1u);
        }
        ++gv;
        cur ^= 1;
    }
}

extern "C" void kernel_launch(void* const* d_in, const int* in_sizes, int n_in,
                              void* d_out, int out_size) {
    const float* list_signal = (const float*)d_in[0];
    const float* B_ext       = (const float*)d_in[1];
    const float* Msat        = (const float*)d_in[2];
    const int*   src_pos     = (const int*)d_in[3];
    const int*   probe_pos   = (const int*)d_in[4];
    const int*   final_board = (const int*)d_in[5];
    float*       out         = (float*)d_out;

    cudaFuncSetAttribute(mm_solver_kernel,
                         cudaFuncAttributeMaxDynamicSharedMemorySize, SMEM_BYTES);
    reset_kernel<<<1, 32>>>();
    mm_solver_kernel<<<NB, NT, SMEM_BYTES>>>(list_signal, B_ext, Msat, src_pos,
                                             probe_pos, final_board, out);
}

// round 15
// speedup vs baseline: 2.1543x; 1.0156x over previous
#include <cuda_runtime.h>

// ---------------------------------------------------------------------------
// Micromagnetic LLG solver (RK4, 5-pt exchange laplacian, SOT, demag-z).
// Round 12: split-phase grid barrier + ALU-slot trim.
//   - arrive (atomicAdd) immediately after interior publish; the interior
//     smem staging + signal loads for the NEXT pair run between arrive and
//     wait, overlapping the ~2us barrier RTT with useful work
//   - meta decoded once into registers (lim/inter/sj/pj): no bitfield
//     extraction in the 8-stage hot loop
//   - otherwise round-11 structure: vertical 3-cell segments (768 thr),
//     register-resident N/S, two-step fusion (halo 8), 2 replicas,
//     shrinking cone, float4 smem ping-pong, central-counter barrier
// ---------------------------------------------------------------------------

#define NXg 256
#define NYg 256
#define NCELL (NXg * NYg)
#define TSTEPS 256
#define NSRC 3
#define NPROBE 5
#define RELAX_STEPS 100

#define NB 128            // 2 replicas x 64 tiles, 1 CTA/SM, single wave
#define NT 768            // 16 segments x 48 columns
#define NSEG 16
#define NQ 3              // cells per thread (vertical)
#define HALO 8
#define EXT 48            // 32 + 2*8
#define MAXC (EXT * EXT)  // 2304 = 768*3
#define SMEM_BYTES (2 * MAXC * (int)sizeof(float4))   // 73728
#define NFUSED ((RELAX_STEPS + TSTEPS) / 2)           // 178
#define RELAX_FUSED (RELAX_STEPS / 2)                 // 50

// [replica][parity][cell]
__device__ float4 g_fld[2][2][NCELL];
__device__ unsigned int g_cnt[2];
__device__ volatile unsigned int g_gen[2];

__global__ void reset_kernel() {
    if (threadIdx.x < 2) {
        g_cnt[threadIdx.x] = 0u;
        g_gen[threadIdx.x] = 0u;
    }
}

// Arrival half of the split barrier: 64 single-lane arrivals on one counter.
// Winner resets the counter and publishes the generation.
__device__ __forceinline__ void gbar_arrive(int r, unsigned int v) {
    if (atomicAdd(&g_cnt[r], 1u) == 63u) {
        g_cnt[r] = 0u;
        __threadfence();
        g_gen[r] = v;
    }
}

__global__ void __launch_bounds__(NT, 1)
mm_solver_kernel(const float* __restrict__ sigarr,   // [2, TSTEPS, NSRC]
                 const float* __restrict__ Bext,     // [1,3,NX,NY]
                 const float* __restrict__ msat,
                 const int*   __restrict__ srcp,     // [NSRC,2]
                 const int*   __restrict__ probep,   // [NPROBE,2]
                 const int*   __restrict__ fb,
                 float*       __restrict__ out)      // [2, TSTEPS, NPROBE]
{
    extern __shared__ float4 sb4[];        // [2][MAXC] ping-pong stage buffers

    const int tid = threadIdx.x;
    const int r  = blockIdx.x >> 6;        // replica = signal index
    const int tb = blockIdx.x & 63;
    const int tx = tb >> 3, ty = tb & 7;
    const int x0 = tx * 32, y0 = ty * 32;

    const int seg = tid / EXT;             // 0..15
    const int sy  = tid - seg * EXT;       // 0..47
    const int gy  = y0 - HALO + sy;
    const int c0  = seg * NQ * EXT + sy;   // smem index of q=0 cell
    const int offW = (sy > 0 && gy > 0) ? -1 : 0;            // W/E clamp (y)
    const int offE = (sy < EXT - 1 && gy < NYg - 1) ? 1 : 0;
    const int nIdx = (seg > 0) ? c0 - EXT : c0;              // q=0 N boundary
    const int sIdx = (seg < NSEG - 1) ? c0 + 3 * EXT : c0 + 2 * EXT; // q=2 S

    // mirror-register fixup for physical x-edge clamp (rows gx=0 / gx=255
    // land mid-segment only in x0==0 seg==2 / x0==224 seg==13 tiles)
    bool mfix = false; int mi = 2;
    if (x0 == 0 && seg == 2)    { mfix = true; mi = 2; }
    if (x0 == 224 && seg == 13) { mfix = true; mi = 0; }

    const float Msat = msat[0];
    const int finalb = fb[0];
    const float ce = (float)(2.0 * 3.5e-12 / ((double)Msat * (5e-8 * 5e-8)));
    const float cd = (float)(-(1.2566370614359172e-06) * (double)Msat);
    const float h  = (float)(175950000000.0 * 5e-12);
    const float h6 = (float)((175950000000.0 * 5e-12) / 6.0);
    const float C_SOT = 1.0e-4f;

    // decoded per-cell state (no bitfield extraction in the hot loop)
    int lim[NQ], sjr[NQ], pjr[NQ], ig[NQ];
    bool inter[NQ];
    float bcx[NQ], bcy[NQ], bcz[NQ];
    float m0x[NQ], m0y[NQ], m0z[NQ];
    float sx_[NQ], sy_[NQ], sz_[NQ];
    float mrelz[NQ];

#pragma unroll
    for (int q = 0; q < NQ; ++q) {
        int sx = NQ * seg + q;                 // 0..47
        int gx = x0 - HALO + sx;
        bool valid = gx >= 0 && gx < NXg && gy >= 0 && gy < NYg;
        inter[q] = valid && gx >= x0 && gx < x0 + 32 && gy >= y0 && gy < y0 + 32;
        int dxn = (sx < HALO) ? (HALO - sx) : (sx >= HALO + 32 ? sx - (HALO + 31) : 0);
        int dyn = (sy < HALO) ? (HALO - sy) : (sy >= HALO + 32 ? sy - (HALO + 31) : 0);
        int d = dxn > dyn ? dxn : dyn;
        lim[q] = valid ? (8 - d) : 0;
        if (lim[q] < 0) lim[q] = 0;
        int gxc = gx < 0 ? 0 : (gx > NXg - 1 ? NXg - 1 : gx);
        int gyc = gy < 0 ? 0 : (gy > NYg - 1 ? NYg - 1 : gy);
        int ign = gxc * NYg + gyc;
        ig[q] = ign;
        bcx[q] = Bext[ign];
        bcy[q] = Bext[NCELL + ign];
        bcz[q] = Bext[2 * NCELL + ign];
        sjr[q] = 0; pjr[q] = 0;
        if (valid) {
#pragma unroll
            for (int k2 = 0; k2 < NSRC; ++k2)
                if (srcp[2 * k2] == gx && srcp[2 * k2 + 1] == gy) sjr[q] = k2 + 1;
            if (inter[q]) {
#pragma unroll
                for (int k2 = 0; k2 < NPROBE; ++k2)
                    if (probep[2 * k2] == gx && probep[2 * k2 + 1] == gy) pjr[q] = k2 + 1;
            }
        }
        m0x[q] = 0.0f; m0y[q] = 1.0f; m0z[q] = 0.0f;
        sx_[q] = 0.0f; sy_[q] = 1.0f; sz_[q] = 0.0f;
        mrelz[q] = 0.0f;
        if (inter[q]) g_fld[r][0][ign] = make_float4(0.0f, 1.0f, 0.0f, 0.0f);
    }

    // initial publish + arrive (instance 1)
    __syncthreads();
    if (tid == 0) {
        __threadfence();
        gbar_arrive(r, 1u);
    }
    unsigned int gv = 1;
    int cur = 0;

    float ax_[NQ], ay_[NQ], az_[NQ];
    float sgA[NQ], sgB[NQ];

    // ---- fused step loop: 50 relax pairs + 128 run pairs ----
#pragma unroll 1
    for (int i = 0; i < NFUSED; ++i) {
        const bool run = (i >= RELAX_FUSED);
        const int  tA  = 2 * i - RELAX_STEPS;       // first half-step time idx
        const float alpha = run ? 0.01f : 0.5f;
        const float inv   = run ? (1.0f / (1.0f + 0.01f * 0.01f))
                                : (1.0f / (1.0f + 0.5f * 0.5f));
        const float* sgb = sigarr + (r * TSTEPS + (run ? tA : 0)) * NSRC;

        // Phase A (between arrive and wait — no neighbor dependency):
        // publish register-resident interior to stage buffer 0, reset
        // accumulators, load signal values.
#pragma unroll
        for (int q = 0; q < NQ; ++q) {
            sgA[q] = 0.0f; sgB[q] = 0.0f;
            ax_[q] = ay_[q] = az_[q] = 0.0f;
            if (inter[q]) {
                sx_[q] = m0x[q]; sy_[q] = m0y[q]; sz_[q] = m0z[q];
                sb4[c0 + q * EXT] = make_float4(m0x[q], m0y[q], m0z[q], 0.0f);
            }
            if (sjr[q] && run) {
                sgA[q] = __ldg(sgb + sjr[q] - 1);
                sgB[q] = __ldg(sgb + NSRC + sjr[q] - 1);
            }
        }

        // Wait half of the split barrier.
        if (tid == 0) {
            while (g_gen[r] < gv) { }
        }
        __syncthreads();
        __threadfence();   // acquire: order halo loads after the observation

        // Phase B: halo cells from L2.
#pragma unroll
        for (int q = 0; q < NQ; ++q) {
            if (lim[q] > 0 && !inter[q]) {
                float4 f = __ldcg(&g_fld[r][cur][ig[q]]);
                m0x[q] = f.x; m0y[q] = f.y; m0z[q] = f.z;
                sx_[q] = f.x; sy_[q] = f.y; sz_[q] = f.z;
                sb4[c0 + q * EXT] = make_float4(f.x, f.y, f.z, 0.0f);
            }
        }
        __syncthreads();

        // 8 RK4 stages (2 full steps); N/S from registers, W/E+bounds from smem
        int p = 0;
#pragma unroll
        for (int st = 0; st < 8; ++st) {
            const int k = st & 3;                  // stage index within step
            const float wk = (k == 1 || k == 2) ? 2.0f : 1.0f;
            const float ck = (k == 2) ? 1.0f : 0.5f;
            const float4* __restrict__ rb = sb4 + p * MAXC;
            float4* __restrict__ wb = sb4 + (p ^ 1) * MAXC;
            float px = 0.0f, py = 0.0f, pz = 0.0f;   // prev-stage value of q-1
#pragma unroll
            for (int q = 0; q < NQ; ++q) {
                const float ox = sx_[q], oy = sy_[q], oz = sz_[q];
                if (st < lim[q]) {
                    const int cq = c0 + q * EXT;
                    float4 nW = rb[cq + offW];
                    float4 nE = rb[cq + offE];
                    float Nx, Ny, Nz, Sx, Sy, Sz;
                    if (q == 0) { float4 t = rb[nIdx]; Nx = t.x; Ny = t.y; Nz = t.z; }
                    else        { Nx = px; Ny = py; Nz = pz; }
                    if (q == NQ - 1) { float4 t = rb[sIdx]; Sx = t.x; Sy = t.y; Sz = t.z; }
                    else             { Sx = sx_[q + 1]; Sy = sy_[q + 1]; Sz = sz_[q + 1]; }
                    float sigv = (st < 4) ? sgA[q] : sgB[q];

                    float lx = Nx + Sx + nW.x + nE.x - 4.0f * ox;
                    float ly = Ny + Sy + nW.y + nE.y - 4.0f * oy;
                    float lz = Nz + Sz + nW.z + nE.z - 4.0f * oz;

                    float Bx = bcx[q] + ce * lx;
                    float By = bcy[q] + ce * ly;
                    float Bz = bcz[q] + ce * lz + cd * oz + sigv;

                    float cx = oy * Bz - oz * By;
                    float cy = oz * Bx - ox * Bz;
                    float cz = ox * By - oy * Bx;
                    float dx = oy * cz - oz * cy;
                    float dy = oz * cx - ox * cz;
                    float dz = ox * cy - oy * cx;
                    float qx = oy * ox;
                    float qy = -(oz * oz + ox * ox);
                    float qz = oy * oz;

                    float kx = -inv * (cx + alpha * dx) + C_SOT * qx;
                    float ky = -inv * (cy + alpha * dy) + C_SOT * qy;
                    float kz = -inv * (cz + alpha * dz) + C_SOT * qz;

                    ax_[q] += wk * kx;
                    ay_[q] += wk * ky;
                    az_[q] += wk * kz;

                    if (k < 3) {
                        float cf = ck * h;
                        sx_[q] = m0x[q] + cf * kx;
                        sy_[q] = m0y[q] + cf * ky;
                        sz_[q] = m0z[q] + cf * kz;
                    } else {
                        sx_[q] = m0x[q] + h6 * ax_[q];
                        sy_[q] = m0y[q] + h6 * ay_[q];
                        sz_[q] = m0z[q] + h6 * az_[q];
                        m0x[q] = sx_[q]; m0y[q] = sy_[q]; m0z[q] = sz_[q];
                        ax_[q] = 0.0f; ay_[q] = 0.0f; az_[q] = 0.0f;
                        if (st == 3) {
                            if (pjr[q] && run) {
                                float v = finalb ? (sz_[q] - mrelz[q]) * Msat : sz_[q];
                                out[(r * TSTEPS + tA) * NPROBE + pjr[q] - 1] = v;
                            }
                        }
                    }
                    if (st < 7)
                        wb[cq] = make_float4(sx_[q], sy_[q], sz_[q], 0.0f);
                }
                px = ox; py = oy; pz = oz;
            }
            // physical x-edge clamp: mirror cell tracks its edge neighbor
            if (mfix) { sx_[1] = sx_[mi]; sy_[1] = sy_[mi]; sz_[1] = sz_[mi]; }
            if (st < 7) { __syncthreads(); p ^= 1; }
        }

        // store interior, capture relaxed z, emit second-half probes (t = tA+1)
#pragma unroll
        for (int q = 0; q < NQ; ++q) {
            if (inter[q]) {
                g_fld[r][cur ^ 1][ig[q]] = make_float4(m0x[q], m0y[q], m0z[q], 0.0f);
                if (i == RELAX_FUSED - 1) mrelz[q] = m0z[q];
                if (pjr[q] && run) {
                    float v = finalb ? (m0z[q] - mrelz[q]) * Msat : m0z[q];
                    out[(r * TSTEPS + tA + 1) * NPROBE + pjr[q] - 1] = v;
                }
            }
        }

        // arrive for the next barrier instance; wait happens next iteration
        __syncthreads();
        if (tid == 0) {
            __threadfence();
            gbar_arrive(r, gv + 1u);
        }
        ++gv;
        cur ^= 1;
    }
}

extern "C" void kernel_launch(void* const* d_in, const int* in_sizes, int n_in,
                              void* d_out, int out_size) {
    const float* list_signal = (const float*)d_in[0];
    const float* B_ext       = (const float*)d_in[1];
    const float* Msat        = (const float*)d_in[2];
    const int*   src_pos     = (const int*)d_in[3];
    const int*   probe_pos   = (const int*)d_in[4];
    const int*   final_board = (const int*)d_in[5];
    float*       out         = (float*)d_out;

    cudaFuncSetAttribute(mm_solver_kernel,
                         cudaFuncAttributeMaxDynamicSharedMemorySize, SMEM_BYTES);
    reset_kernel<<<1, 32>>>();
    mm_solver_kernel<<<NB, NT, SMEM_BYTES>>>(list_signal, B_ext, Msat, src_pos,
                                             probe_pos, final_board, out);
}

// round 16
// speedup vs baseline: 2.8296x; 1.3135x over previous
#include <cuda_runtime.h>

// ---------------------------------------------------------------------------
// Micromagnetic LLG solver (RK4, 5-pt exchange laplacian, SOT, demag-z).
// Round 16: halo-4 / no-cone / 4-step fusion.
//   - physics: per-stencil-hop coupling ce*h ~ 3e-3 -> halo errors reach the
//     interior attenuated by (3e-3)^4 ~ 1e-10; round 12 empirically confirmed
//     this (unloaded d=8 ring, rel_err 0.0). So: halo 4, every cell computes
//     every stage (branch-free), 16 stages per grid sync.
//   - grid syncs 178 -> 89; EXT 48 -> 40 (1600 cells, exactly 2/thread)
//   - thread = vertical 2-cell segment (20 segs x 40 cols = 800 thr);
//     N/S inside the pair from registers, boundary N/S + W/E from smem
//   - physical pad=edge rows (gx=0 even -> lo, gx=255 odd -> hi) land on the
//     smem-clamped boundary read paths: exact, no mirror fixup
//   - keeps: 2 replicas, split-phase central barrier (arrive after store,
//     Phase-A overlap, wait before halo load), float4 smem ping-pong
// ---------------------------------------------------------------------------

#define NXg 256
#define NYg 256
#define NCELL (NXg * NYg)
#define TSTEPS 256
#define NSRC 3
#define NPROBE 5
#define RELAX_STEPS 100

#define NB 128            // 2 replicas x 64 tiles, 1 CTA/SM, single wave
#define NT 800            // 20 segments x 40 columns, 2 cells/thread
#define NSEG 20
#define HALO 4
#define EXT 40
#define MAXC (EXT * EXT)  // 1600
#define GSTEPS 4
#define NGROUPS ((RELAX_STEPS + TSTEPS) / GSTEPS)   // 89
#define RELAX_GROUPS (RELAX_STEPS / GSTEPS)         // 25
#define SMEM_BYTES (2 * MAXC * (int)sizeof(float4)) // 51200

// [replica][parity][cell]
__device__ float4 g_fld[2][2][NCELL];
__device__ unsigned int g_cnt[2];
__device__ volatile unsigned int g_gen[2];

__global__ void reset_kernel() {
    if (threadIdx.x < 2) { g_cnt[threadIdx.x] = 0u; g_gen[threadIdx.x] = 0u; }
}

// Arrival half of the split barrier: 64 single-lane arrivals on one counter.
__device__ __forceinline__ void gbar_arrive(int r, unsigned int v) {
    if (atomicAdd(&g_cnt[r], 1u) == 63u) {
        g_cnt[r] = 0u;
        __threadfence();
        g_gen[r] = v;
    }
}

// LLG torque for one cell (expression text identical to prior rounds).
__device__ __forceinline__ void torque(
    float ox, float oy, float oz,
    float Nx, float Ny, float Nz, float Sx, float Sy, float Sz,
    float Wx, float Wy, float Wz, float Ex, float Ey, float Ez,
    float bx, float by, float bz, float sigv,
    float ce, float cd, float alpha, float inv,
    float& kx, float& ky, float& kz)
{
    const float C_SOT = 1.0e-4f;
    float lx = Nx + Sx + Wx + Ex - 4.0f * ox;
    float ly = Ny + Sy + Wy + Ey - 4.0f * oy;
    float lz = Nz + Sz + Wz + Ez - 4.0f * oz;

    float Bx = bx + ce * lx;
    float By = by + ce * ly;
    float Bz = bz + ce * lz + cd * oz + sigv;

    float cx = oy * Bz - oz * By;
    float cy = oz * Bx - ox * Bz;
    float cz = ox * By - oy * Bx;
    float dx = oy * cz - oz * cy;
    float dy = oz * cx - ox * cz;
    float dz = ox * cy - oy * cx;
    float qx = oy * ox;
    float qy = -(oz * oz + ox * ox);
    float qz = oy * oz;

    kx = -inv * (cx + alpha * dx) + C_SOT * qx;
    ky = -inv * (cy + alpha * dy) + C_SOT * qy;
    kz = -inv * (cz + alpha * dz) + C_SOT * qz;
}

__global__ void __launch_bounds__(NT, 1)
mm_solver_kernel(const float* __restrict__ sigarr,   // [2, TSTEPS, NSRC]
                 const float* __restrict__ Bext,     // [1,3,NX,NY]
                 const float* __restrict__ msat,
                 const int*   __restrict__ srcp,     // [NSRC,2]
                 const int*   __restrict__ probep,   // [NPROBE,2]
                 const int*   __restrict__ fb,
                 float*       __restrict__ out)      // [2, TSTEPS, NPROBE]
{
    extern __shared__ float4 sb4[];        // [2][MAXC] ping-pong stage buffers

    const int tid = threadIdx.x;
    const int r  = blockIdx.x >> 6;        // replica = signal index
    const int tb = blockIdx.x & 63;
    const int tx = tb >> 3, ty = tb & 7;
    const int x0 = tx * 32, y0 = ty * 32;

    const int seg  = tid / EXT;            // 0..19
    const int colI = tid - seg * EXT;      // 0..39
    const int gy   = y0 - HALO + colI;
    const int gx0  = x0 - HALO + 2 * seg;  // lo cell row (even)
    const int c0   = (2 * seg) * EXT + colI;
    const int c1   = c0 + EXT;

    // clamped neighbor smem offsets (clamp-to-self serves both the physical
    // pad=edge rule and the halo truncation)
    const int offW = (colI > 0       && gy > 0      ) ? -1 : 0;
    const int offE = (colI < EXT - 1 && gy < NYg - 1) ? 1 : 0;
    const int nIdx = (seg > 0        && gx0 > 0         ) ? c0 - EXT : c0;
    const int sIdx = (seg < NSEG - 1 && gx0 + 1 < NXg-1 ) ? c1 + EXT : c1;

    const float Msat = msat[0];
    const int finalb = fb[0];
    const float ce = (float)(2.0 * 3.5e-12 / ((double)Msat * (5e-8 * 5e-8)));
    const float cd = (float)(-(1.2566370614359172e-06) * (double)Msat);
    const float h  = (float)(175950000000.0 * 5e-12);
    const float h6 = (float)((175950000000.0 * 5e-12) / 6.0);

    int ig[2], sjr[2], pjr[2];
    bool inter[2];
    float bcx[2], bcy[2], bcz[2];
    float m0x[2], m0y[2], m0z[2];
    float sx_[2], sy_[2], sz_[2];
    float mrelz[2];

#pragma unroll
    for (int q = 0; q < 2; ++q) {
        int gx = gx0 + q;
        bool valid = gx >= 0 && gx < NXg && gy >= 0 && gy < NYg;
        inter[q] = valid && gx >= x0 && gx < x0 + 32 && gy >= y0 && gy < y0 + 32;
        int gxc = gx < 0 ? 0 : (gx > NXg - 1 ? NXg - 1 : gx);
        int gyc = gy < 0 ? 0 : (gy > NYg - 1 ? NYg - 1 : gy);
        int ign = gxc * NYg + gyc;
        ig[q] = ign;
        bcx[q] = Bext[ign];
        bcy[q] = Bext[NCELL + ign];
        bcz[q] = Bext[2 * NCELL + ign];
        sjr[q] = 0; pjr[q] = 0;
        if (valid) {
#pragma unroll
            for (int k2 = 0; k2 < NSRC; ++k2)
                if (srcp[2 * k2] == gx && srcp[2 * k2 + 1] == gy) sjr[q] = k2 + 1;
            if (inter[q]) {
#pragma unroll
                for (int k2 = 0; k2 < NPROBE; ++k2)
                    if (probep[2 * k2] == gx && probep[2 * k2 + 1] == gy) pjr[q] = k2 + 1;
            }
        }
        m0x[q] = 0.0f; m0y[q] = 1.0f; m0z[q] = 0.0f;
        sx_[q] = 0.0f; sy_[q] = 1.0f; sz_[q] = 0.0f;
        mrelz[q] = 0.0f;
        if (inter[q]) g_fld[r][0][ign] = make_float4(0.0f, 1.0f, 0.0f, 0.0f);
    }

    // initial publish + arrive (instance 1)
    __syncthreads();
    if (tid == 0) {
        __threadfence();
        gbar_arrive(r, 1u);
    }
    unsigned int gv = 1;
    int cur = 0;

    float ax_[2], ay_[2], az_[2];
    float sg[4][2];

    // ---- group loop: 25 relax groups + 64 run groups, 4 steps each ----
#pragma unroll 1
    for (int i = 0; i < NGROUPS; ++i) {
        const bool run = (i >= RELAX_GROUPS);
        const int  t0  = GSTEPS * i - RELAX_STEPS;   // first step's time index
        const float alpha = run ? 0.01f : 0.5f;
        const float inv   = run ? (1.0f / (1.0f + 0.01f * 0.01f))
                                : (1.0f / (1.0f + 0.5f * 0.5f));
        const float* sgb = sigarr + (r * TSTEPS + (run ? t0 : 0)) * NSRC;

        // Phase A (between arrive and wait — no neighbor dependency):
        // publish interior regs to stage buffer 0, reset acc, load signals.
#pragma unroll
        for (int q = 0; q < 2; ++q) {
            ax_[q] = ay_[q] = az_[q] = 0.0f;
#pragma unroll
            for (int sub = 0; sub < 4; ++sub) sg[sub][q] = 0.0f;
            if (inter[q]) {
                sx_[q] = m0x[q]; sy_[q] = m0y[q]; sz_[q] = m0z[q];
                sb4[q ? c1 : c0] = make_float4(m0x[q], m0y[q], m0z[q], 0.0f);
            }
            if (sjr[q] && run) {
#pragma unroll
                for (int sub = 0; sub < 4; ++sub)
                    sg[sub][q] = __ldg(sgb + sub * NSRC + sjr[q] - 1);
            }
        }

        // Wait half of the split barrier.
        if (tid == 0) {
            while (g_gen[r] < gv) { }
        }
        __syncthreads();
        __threadfence();   // acquire: order halo loads after the observation

        // Phase B: non-interior cells from L2 (clamped index; always finite).
#pragma unroll
        for (int q = 0; q < 2; ++q) {
            if (!inter[q]) {
                float4 f = __ldcg(&g_fld[r][cur][ig[q]]);
                m0x[q] = f.x; m0y[q] = f.y; m0z[q] = f.z;
                sx_[q] = f.x; sy_[q] = f.y; sz_[q] = f.z;
                sb4[q ? c1 : c0] = make_float4(f.x, f.y, f.z, 0.0f);
            }
        }
        __syncthreads();

        // 16 RK4 stages (4 full steps), branch-free; N/S of the pair interior
        // from registers, boundary N/S + W/E from smem.
        int p = 0;
#pragma unroll
        for (int st = 0; st < 16; ++st) {
            const int k   = st & 3;
            const int sub = st >> 2;
            const float wk = (k == 1 || k == 2) ? 2.0f : 1.0f;
            const float ck = (k == 2) ? 1.0f : 0.5f;
            const float4* __restrict__ rb = sb4 + p * MAXC;
            float4* __restrict__ wb = sb4 + (p ^ 1) * MAXC;

            float4 Nt = rb[nIdx];
            float4 St = rb[sIdx];
            float4 w0 = rb[c0 + offW];
            float4 e0 = rb[c0 + offE];
            float4 w1 = rb[c1 + offW];
            float4 e1 = rb[c1 + offE];

            const float o0x = sx_[0], o0y = sy_[0], o0z = sz_[0];
            const float o1x = sx_[1], o1y = sy_[1], o1z = sz_[1];

            float k0x, k0y, k0z, k1x, k1y, k1z;
            torque(o0x, o0y, o0z,
                   Nt.x, Nt.y, Nt.z,  o1x, o1y, o1z,
                   w0.x, w0.y, w0.z,  e0.x, e0.y, e0.z,
                   bcx[0], bcy[0], bcz[0], sg[sub][0],
                   ce, cd, alpha, inv, k0x, k0y, k0z);
            torque(o1x, o1y, o1z,
                   o0x, o0y, o0z,  St.x, St.y, St.z,
                   w1.x, w1.y, w1.z,  e1.x, e1.y, e1.z,
                   bcx[1], bcy[1], bcz[1], sg[sub][1],
                   ce, cd, alpha, inv, k1x, k1y, k1z);

            ax_[0] += wk * k0x; ay_[0] += wk * k0y; az_[0] += wk * k0z;
            ax_[1] += wk * k1x; ay_[1] += wk * k1y; az_[1] += wk * k1z;

            if (k < 3) {
                float cf = ck * h;
                sx_[0] = m0x[0] + cf * k0x;
                sy_[0] = m0y[0] + cf * k0y;
                sz_[0] = m0z[0] + cf * k0z;
                sx_[1] = m0x[1] + cf * k1x;
                sy_[1] = m0y[1] + cf * k1y;
                sz_[1] = m0z[1] + cf * k1z;
            } else {
                // finalize this step's m; republish for the next step
                sx_[0] = m0x[0] + h6 * ax_[0];
                sy_[0] = m0y[0] + h6 * ay_[0];
                sz_[0] = m0z[0] + h6 * az_[0];
                sx_[1] = m0x[1] + h6 * ax_[1];
                sy_[1] = m0y[1] + h6 * ay_[1];
                sz_[1] = m0z[1] + h6 * az_[1];
                m0x[0] = sx_[0]; m0y[0] = sy_[0]; m0z[0] = sz_[0];
                m0x[1] = sx_[1]; m0y[1] = sy_[1]; m0z[1] = sz_[1];
                ax_[0] = ay_[0] = az_[0] = 0.0f;
                ax_[1] = ay_[1] = az_[1] = 0.0f;
                if (run) {
#pragma unroll
                    for (int q = 0; q < 2; ++q) {
                        if (pjr[q]) {
                            float v = finalb ? (sz_[q] - mrelz[q]) * Msat : sz_[q];
                            out[(r * TSTEPS + t0 + sub) * NPROBE + pjr[q] - 1] = v;
                        }
                    }
                }
            }
            if (st < 15) {
                wb[c0] = make_float4(sx_[0], sy_[0], sz_[0], 0.0f);
                wb[c1] = make_float4(sx_[1], sy_[1], sz_[1], 0.0f);
                __syncthreads();
                p ^= 1;
            }
        }

        // store interior, capture relaxed z
#pragma unroll
        for (int q = 0; q < 2; ++q) {
            if (inter[q]) {
                g_fld[r][cur ^ 1][ig[q]] = make_float4(m0x[q], m0y[q], m0z[q], 0.0f);
                if (i == RELAX_GROUPS - 1) mrelz[q] = m0z[q];
            }
        }

        // arrive for the next barrier instance; wait happens next iteration
        __syncthreads();
        if (tid == 0) {
            __threadfence();
            gbar_arrive(r, gv + 1u);
        }
        ++gv;
        cur ^= 1;
    }
}

extern "C" void kernel_launch(void* const* d_in, const int* in_sizes, int n_in,
                              void* d_out, int out_size) {
    const float* list_signal = (const float*)d_in[0];
    const float* B_ext       = (const float*)d_in[1];
    const float* Msat        = (const float*)d_in[2];
    const int*   src_pos     = (const int*)d_in[3];
    const int*   probe_pos   = (const int*)d_in[4];
    const int*   final_board = (const int*)d_in[5];
    float*       out         = (float*)d_out;

    cudaFuncSetAttribute(mm_solver_kernel,
                         cudaFuncAttributeMaxDynamicSharedMemorySize, SMEM_BYTES);
    reset_kernel<<<1, 32>>>();
    mm_solver_kernel<<<NB, NT, SMEM_BYTES>>>(list_signal, B_ext, Msat, src_pos,
                                             probe_pos, final_board, out);
}